// round 14
// baseline (speedup 1.0000x reference)
#include <cuda_runtime.h>
#include <cuda_fp16.h>

// GCN_3831110828646 — restructured GCN, bucketed edges + prescaled fp16 + HMMA gemm:
//   g_csrc holds PRE-SHIFTED byte offsets (src << 7) of 128B xh rows.
//   xh[s] = fp16( x[s] * dinv[s] )
//   ah[d] = fp16( dinv[d] * ( sum_b xh[s_b] + xh[d] ) )      (8-lane rows; flat predicated loop)
//   z[n]  = dinv[n] * dot( relu(ah[n] @ W1h + b1), W2@Wl )   (mma.m16n8k16 + fused epilogue)
//   out[d]= dinv[d] * ( sum_b z[s_b] + z[d] ) + (b2@Wl + bl) (scalar gather, int4 idx loads)

#define NMAX 100000
#define EMAX 1600000
#define CAP  64

__device__ int          g_idx64;
__device__ int          g_count[NMAX];
__device__ float        g_dinv[NMAX];
__device__ int          g_csrc[NMAX * CAP];  // 25.6 MB, entries are (src << 7)
__device__ unsigned int g_xh[NMAX * 32];     // prescaled x fp16: 32 half2 per row (128B)
__device__ unsigned int g_ah[NMAX * 32];     // aggregated a fp16: 32 half2 per row
__device__ __half       g_w1t[128 * 64];     // W1 transposed [n][k] fp16
__device__ float        g_z[NMAX];
__device__ float        g_w2l[128];
__device__ float        g_cb;

__device__ __forceinline__ __half2 h2add(__half2 a, __half2 b) { return __hadd2(a, b); }
__device__ __forceinline__ __half2 as_h2(unsigned int u) { return *(__half2*)&u; }
__device__ __forceinline__ unsigned int as_u(__half2 h) { return *(unsigned int*)&h; }

// ---------------------------------------------------------------------------
__global__ void k_prep0(const int* __restrict__ ei, int n,
                        const float* __restrict__ W1,
                        const float* __restrict__ W2, const float* __restrict__ b2,
                        const float* __restrict__ Wl, const float* __restrict__ bl) {
    int gid = blockIdx.x * blockDim.x + threadIdx.x;
    if (gid < n) g_count[gid] = 0;
    if (blockIdx.x == 0) {
        int c = threadIdx.x;
        if (c < 128) {
            float s = 0.f;
            for (int k = 0; k < 100; k++) s += W2[c * 100 + k] * Wl[k];
            g_w2l[c] = s;
        }
        if (c == 0) {
            float t = 0.f;
            for (int k = 0; k < 100; k++) t += b2[k] * Wl[k];
            g_cb = t + bl[0];
            int is64 = 1;
            for (int j = 0; j < 64; j++)
                if (ei[2 * j + 1] != 0) { is64 = 0; break; }
            g_idx64 = is64;
        }
    }
    if (blockIdx.x == 1) {
        for (int i = threadIdx.x; i < 128 * 64; i += blockDim.x) {
            int nl = i >> 6, k = i & 63;
            g_w1t[i] = __float2half(W1[k * 128 + nl]);   // W1t[n][k] = W1[k][n]
        }
    }
}

__device__ __forceinline__ int load_src(const void* ei, int E, int e, int n) {
    int v = g_idx64 ? (int)((const long long*)ei)[e] : ((const int*)ei)[e];
    return min(max(v, 0), n - 1);
}
__device__ __forceinline__ int load_dst(const void* ei, int E, int e, int n) {
    int v = g_idx64 ? (int)((const long long*)ei)[E + e] : ((const int*)ei)[E + e];
    return min(max(v, 0), n - 1);
}

// One edge per thread; stores PRE-SHIFTED src (byte offset of its 128B row).
__global__ void k_fill(const void* __restrict__ ei, int E, int n) {
    int e = blockIdx.x * blockDim.x + threadIdx.x;
    if (e < E) {
        int d = load_dst(ei, E, e, n);
        int p = atomicAdd(&g_count[d], 1);
        if (p < CAP) g_csrc[d * CAP + p] = load_src(ei, E, e, n) << 7;
    }
}

// x -> fp16 prescaled by dinv[row]; store dinv. One float4 per thread.
__global__ void k_conv(const float* __restrict__ x, int n) {
    int i = blockIdx.x * blockDim.x + threadIdx.x;   // over n*16 float4s
    if (i >= n * 16) return;
    int row = i >> 4;
    float din = rsqrtf((float)(min(g_count[row], CAP) + 1));
    float4 v = ((const float4*)x)[i];
    __half2 h0 = __floats2half2_rn(v.x * din, v.y * din);
    __half2 h1 = __floats2half2_rn(v.z * din, v.w * din);
    uint2 u;
    u.x = *(unsigned int*)&h0;
    u.y = *(unsigned int*)&h1;
    ((uint2*)g_xh)[i] = u;
    if ((i & 15) == 0) g_dinv[row] = din;
}

// ---------------------------------------------------------------------------
// Aggregation: one warp per node, row = 8 lanes x uint4 (128B); 4 groups each
// take a different edge per instruction. 32 bucket offsets preloaded in ONE
// LDG; fixed 4-trip fully-unrolled predicated inner loop (no branches), shfls
// unconditional, 8 row-LDGs batched per chunk (MLP=8).
__global__ void k_agg1(int n) {
    int warp = (blockIdx.x * blockDim.x + threadIdx.x) >> 5;
    int lane = threadIdx.x & 31;
    if (warp >= n) return;
    int d = warp;
    int g = lane >> 3, l8 = lane & 7;
    int lby = l8 * 16;                               // lane byte offset in row

    const char* xhb = (const char*)g_xh;
    int maxoff = (n - 1) << 7;

    uint4 sv = make_uint4(0u, 0u, 0u, 0u);
    if (g == 0) sv = *(const uint4*)(xhb + d * 128 + lby);   // self term
    __half2 a0[4] = { as_h2(sv.x), as_h2(sv.y), as_h2(sv.z), as_h2(sv.w) };
    __half2 a1[4];
    #pragma unroll
    for (int k = 0; k < 4; k++) a1[k] = as_h2(0u);

    int bko = d * CAP;
    int deg = min(g_count[d], CAP);
    for (int base = 0; base < deg; base += 32) {     // warp-uniform
        int cnt = min(32, deg - base);
        int off = 0;
        if (lane < cnt) off = g_csrc[bko + base + lane];   // one LDG: 32 offsets
        #pragma unroll
        for (int t = 0; t < 4; t++) {
            int j0 = g + t * 8;
            int j1 = j0 + 4;
            int o0 = __shfl_sync(0xffffffff, off, j0);     // uniform
            int o1 = __shfl_sync(0xffffffff, off, j1);
            o0 = min(max(o0, 0), maxoff);
            o1 = min(max(o1, 0), maxoff);
            if (j0 < cnt) {
                uint4 r = *(const uint4*)(xhb + o0 + lby);
                a0[0] = h2add(a0[0], as_h2(r.x));
                a0[1] = h2add(a0[1], as_h2(r.y));
                a0[2] = h2add(a0[2], as_h2(r.z));
                a0[3] = h2add(a0[3], as_h2(r.w));
            }
            if (j1 < cnt) {
                uint4 r = *(const uint4*)(xhb + o1 + lby);
                a1[0] = h2add(a1[0], as_h2(r.x));
                a1[1] = h2add(a1[1], as_h2(r.y));
                a1[2] = h2add(a1[2], as_h2(r.z));
                a1[3] = h2add(a1[3], as_h2(r.w));
            }
        }
    }
    #pragma unroll
    for (int k = 0; k < 4; k++) a0[k] = h2add(a0[k], a1[k]);

    // cross-group reduce
    #pragma unroll
    for (int off2 = 8; off2 <= 16; off2 <<= 1) {
        #pragma unroll
        for (int k = 0; k < 4; k++) {
            unsigned int o = __shfl_xor_sync(0xffffffff, as_u(a0[k]), off2);
            a0[k] = h2add(a0[k], as_h2(o));
        }
    }

    if (g == 0) {   // lanes 0..7 hold the full row sum
        float din = g_dinv[d];
        uint4 u;
        #pragma unroll
        for (int k = 0; k < 4; k++) {
            float2 f = __half22float2(a0[k]);
            __half2 h = __floats2half2_rn(f.x * din, f.y * din);
            ((unsigned int*)&u)[k] = as_u(h);
        }
        ((uint4*)g_ah)[d * 8 + l8] = u;
    }
}

// ---------------------------------------------------------------------------
// z[n] = dinv[n] * dot(relu(ah[n] @ W1 + b1), w2l) via mma.m16n8k16.
#define W1T_STRIDE 72
__global__ void __launch_bounds__(256) k_gemm(const float* __restrict__ b1, int n) {
    __shared__ __half w1s[128 * W1T_STRIDE];   // 18 KB
    __shared__ float  b1s[128];
    __shared__ float  ws[128];

    int tid = threadIdx.x;
    for (int i = tid; i < 2048; i += 256) {
        int nl = i >> 4, kq = i & 15;
        *(uint2*)&w1s[nl * W1T_STRIDE + kq * 4] = ((const uint2*)g_w1t)[i];
    }
    if (tid < 128) { b1s[tid] = b1[tid]; ws[tid] = g_w2l[tid]; }
    __syncthreads();

    int w = tid >> 5, lane = tid & 31;
    int gid = lane >> 2, tg = lane & 3;
    int n0 = (blockIdx.x * 8 + w) * 16;
    if (n0 >= n) return;

    int rA = min(n0 + gid, n - 1);
    int rB = min(n0 + gid + 8, n - 1);

    unsigned int a[4][4];
    #pragma unroll
    for (int kk = 0; kk < 4; kk++) {
        int baseA = rA * 32 + kk * 8;
        int baseB = rB * 32 + kk * 8;
        a[kk][0] = g_ah[baseA + tg];
        a[kk][1] = g_ah[baseB + tg];
        a[kk][2] = g_ah[baseA + tg + 4];
        a[kk][3] = g_ah[baseB + tg + 4];
    }

    float zp0 = 0.f, zp1 = 0.f;
    #pragma unroll
    for (int nc = 0; nc < 16; nc++) {
        float c0 = 0.f, c1 = 0.f, c2 = 0.f, c3 = 0.f;
        int nrow = nc * 8 + gid;
        const unsigned int* w1row = (const unsigned int*)&w1s[nrow * W1T_STRIDE];
        #pragma unroll
        for (int kk = 0; kk < 4; kk++) {
            unsigned int b0 = w1row[kk * 8 + tg];
            unsigned int b1r = w1row[kk * 8 + tg + 4];
            asm volatile(
                "mma.sync.aligned.m16n8k16.row.col.f32.f16.f16.f32 "
                "{%0,%1,%2,%3}, {%4,%5,%6,%7}, {%8,%9}, {%0,%1,%2,%3};"
                : "+f"(c0), "+f"(c1), "+f"(c2), "+f"(c3)
                : "r"(a[kk][0]), "r"(a[kk][1]), "r"(a[kk][2]), "r"(a[kk][3]),
                  "r"(b0), "r"(b1r));
        }
        int j0 = nc * 8 + tg * 2;
        float2 bb = *(const float2*)&b1s[j0];
        float2 ww = *(const float2*)&ws[j0];
        zp0 += fmaxf(c0 + bb.x, 0.f) * ww.x + fmaxf(c1 + bb.y, 0.f) * ww.y;
        zp1 += fmaxf(c2 + bb.x, 0.f) * ww.x + fmaxf(c3 + bb.y, 0.f) * ww.y;
    }

    #pragma unroll
    for (int o = 1; o < 4; o <<= 1) {
        zp0 += __shfl_xor_sync(0xffffffff, zp0, o);
        zp1 += __shfl_xor_sync(0xffffffff, zp1, o);
    }
    if (tg == 0) {
        int nodeA = n0 + gid, nodeB = n0 + gid + 8;
        if (nodeA < n) g_z[nodeA] = g_dinv[nodeA] * zp0;
        if (nodeB < n) g_z[nodeB] = g_dinv[nodeB] * zp1;
    }
}

// ---------------------------------------------------------------------------
// out[d] = dinv[d]*(sum z[src] + z[d]) + cb. int4 loads of 4 offsets/step.
__global__ void k_agg2(float* __restrict__ out, int n) {
    int d = blockIdx.x * blockDim.x + threadIdx.x;
    if (d >= n) return;
    float s = g_z[d];
    const int4* bkt = (const int4*)&g_csrc[d * CAP];
    int deg = min(g_count[d], CAP);
    int nq = (deg + 3) >> 2;
    for (int q = 0; q < nq; q++) {
        int4 o = bkt[q];
        int i0 = q * 4;
        int s0 = min(max(o.x >> 7, 0), n - 1);
        int s1 = min(max(o.y >> 7, 0), n - 1);
        int s2 = min(max(o.z >> 7, 0), n - 1);
        int s3 = min(max(o.w >> 7, 0), n - 1);
        float v = 0.f;
        if (i0 + 0 < deg) v += g_z[s0];
        if (i0 + 1 < deg) v += g_z[s1];
        if (i0 + 2 < deg) v += g_z[s2];
        if (i0 + 3 < deg) v += g_z[s3];
        s += v;
    }
    out[d] = g_dinv[d] * s + g_cb;
}

// ---------------------------------------------------------------------------
extern "C" void kernel_launch(void* const* d_in, const int* in_sizes, int n_in,
                              void* d_out, int out_size) {
    const float* x   = (const float*)d_in[0];
    const void*  ei  = d_in[1];
    const float* W1  = (const float*)d_in[2];
    const float* b1  = (const float*)d_in[3];
    const float* W2  = (const float*)d_in[4];
    const float* b2  = (const float*)d_in[5];
    const float* Wl  = (const float*)d_in[6];
    const float* bl  = (const float*)d_in[7];
    float*       out = (float*)d_out;

    int n = in_sizes[0] / 64;
    int E = in_sizes[1] / 2;

    int nb = (n + 255) / 256;
    int eb = (E + 255) / 256;
    int cb = (n * 16 + 255) / 256;

    k_prep0<<<nb, 256>>>((const int*)ei, n, W1, W2, b2, Wl, bl);
    k_fill <<<eb, 256>>>(ei, E, n);
    k_conv <<<cb, 256>>>(x, n);
    k_agg1 <<<(n + 7) / 8, 256>>>(n);
    k_gemm <<<(n + 127) / 128, 256>>>(b1, n);
    k_agg2 <<<nb, 256>>>(out, n);
}

// round 15
// speedup vs baseline: 1.1186x; 1.1186x over previous
#include <cuda_runtime.h>
#include <cuda_fp16.h>

// GCN_3831110828646 — restructured GCN, bucketed edges + prescaled fp16 + HMMA gemm:
//   xh[s] = fp16( x[s] * dinv[s] )
//   ah[d] = fp16( dinv[d] * ( sum_b xh[s_b] + xh[d] ) )      (8-lane rows; uniform SHFL.IDX loop)
//   z[n]  = dinv[n] * dot( relu(ah[n] @ W1h + b1), W2@Wl )   (mma.m16n8k16 + fused epilogue)
//   out[d]= dinv[d] * ( sum_b z[s_b] + z[d] ) + (b2@Wl + bl) (scalar gather, int4 idx loads)
// Self-cleaning counts: g_count starts zero (BSS) and k_agg2 re-zeroes after
// use, so no n-wide zeroing pass is needed per call.

#define NMAX 100000
#define EMAX 1600000
#define CAP  64

__device__ int          g_idx64;
__device__ int          g_count[NMAX];       // ALWAYS zero at kernel_launch entry
__device__ float        g_dinv[NMAX];
__device__ int          g_csrc[NMAX * CAP];  // 25.6 MB bucket array
__device__ unsigned int g_xh[NMAX * 32];     // prescaled x fp16: 32 half2 per row (128B)
__device__ unsigned int g_ah[NMAX * 32];     // aggregated a fp16: 32 half2 per row
__device__ __half       g_w1t[128 * 64];     // W1 transposed [n][k] fp16
__device__ float        g_z[NMAX];
__device__ float        g_w2l[128];
__device__ float        g_cb;

__device__ __forceinline__ __half2 h2add(__half2 a, __half2 b) { return __hadd2(a, b); }
__device__ __forceinline__ __half2 as_h2(unsigned int u) { return *(__half2*)&u; }
__device__ __forceinline__ unsigned int as_u(__half2 h) { return *(unsigned int*)&h; }

// ---------------------------------------------------------------------------
// 2 blocks only: block 0 = w2l/cb + dtype detect; block 1 = W1 fp16 transpose.
__global__ void k_prep0(const int* __restrict__ ei,
                        const float* __restrict__ W1,
                        const float* __restrict__ W2, const float* __restrict__ b2,
                        const float* __restrict__ Wl, const float* __restrict__ bl) {
    if (blockIdx.x == 0) {
        int c = threadIdx.x;
        if (c < 128) {
            float s = 0.f;
            for (int k = 0; k < 100; k++) s += W2[c * 100 + k] * Wl[k];
            g_w2l[c] = s;
        }
        if (c == 0) {
            float t = 0.f;
            for (int k = 0; k < 100; k++) t += b2[k] * Wl[k];
            g_cb = t + bl[0];
            int is64 = 1;
            for (int j = 0; j < 64; j++)
                if (ei[2 * j + 1] != 0) { is64 = 0; break; }
            g_idx64 = is64;
        }
    } else {
        for (int i = threadIdx.x; i < 128 * 64; i += blockDim.x) {
            int nl = i >> 6, k = i & 63;
            g_w1t[i] = __float2half(W1[k * 128 + nl]);   // W1t[n][k] = W1[k][n]
        }
    }
}

__device__ __forceinline__ int load_src(const void* ei, int E, int e, int n) {
    int v = g_idx64 ? (int)((const long long*)ei)[e] : ((const int*)ei)[e];
    return min(max(v, 0), n - 1);
}
__device__ __forceinline__ int load_dst(const void* ei, int E, int e, int n) {
    int v = g_idx64 ? (int)((const long long*)ei)[E + e] : ((const int*)ei)[E + e];
    return min(max(v, 0), n - 1);
}

// One edge per thread (proven form). Counts are zero on entry (see header).
__global__ void k_fill(const void* __restrict__ ei, int E, int n) {
    int e = blockIdx.x * blockDim.x + threadIdx.x;
    if (e < E) {
        int d = load_dst(ei, E, e, n);
        int p = atomicAdd(&g_count[d], 1);
        if (p < CAP) g_csrc[d * CAP + p] = load_src(ei, E, e, n);
    }
}

// x -> fp16 prescaled by dinv[row]; store dinv. One float4 per thread.
__global__ void k_conv(const float* __restrict__ x, int n) {
    int i = blockIdx.x * blockDim.x + threadIdx.x;   // over n*16 float4s
    if (i >= n * 16) return;
    int row = i >> 4;
    float din = rsqrtf((float)(min(g_count[row], CAP) + 1));
    float4 v = ((const float4*)x)[i];
    __half2 h0 = __floats2half2_rn(v.x * din, v.y * din);
    __half2 h1 = __floats2half2_rn(v.z * din, v.w * din);
    uint2 u;
    u.x = *(unsigned int*)&h0;
    u.y = *(unsigned int*)&h1;
    ((uint2*)g_xh)[i] = u;
    if ((i & 15) == 0) g_dinv[row] = din;
}

// ---------------------------------------------------------------------------
// Aggregation (round-13 proven form, 32 regs / 83% occ): one warp per node,
// row = 8 lanes x uint4 (128B); 4 groups take different edges per instruction.
// 32 bucket indices preloaded in ONE LDG; SHFL.IDX with warp-uniform trip
// count; only loads/adds predicated.
__global__ void k_agg1(int n) {
    int warp = (blockIdx.x * blockDim.x + threadIdx.x) >> 5;
    int lane = threadIdx.x & 31;
    if (warp >= n) return;
    int d = warp;
    int g = lane >> 3, l8 = lane & 7;

    const uint4* xh4 = (const uint4*)g_xh;

    uint4 sv = make_uint4(0u, 0u, 0u, 0u);
    if (g == 0) sv = xh4[d * 8 + l8];            // self term (prescaled by dinv[d])
    __half2 a0[4] = { as_h2(sv.x), as_h2(sv.y), as_h2(sv.z), as_h2(sv.w) };
    __half2 a1[4];
    #pragma unroll
    for (int k = 0; k < 4; k++) a1[k] = as_h2(0u);

    int bko = d * CAP;
    int deg = min(g_count[d], CAP);
    for (int base = 0; base < deg; base += 32) {
        int cnt = min(32, deg - base);             // warp-uniform
        int idx = 0;
        if (lane < cnt) idx = g_csrc[bko + base + lane];   // one LDG: 32 indices
        int nsteps = (cnt + 7) >> 3;               // warp-uniform trip count
        for (int t = 0; t < nsteps; t++) {
            int j0 = g + t * 8;
            int j1 = j0 + 4;
            int s0 = __shfl_sync(0xffffffff, idx, j0);   // uniform: all lanes
            int s1 = __shfl_sync(0xffffffff, idx, j1);
            s0 = min(max(s0, 0), n - 1);
            s1 = min(max(s1, 0), n - 1);
            if (j0 < cnt) {
                uint4 r0 = xh4[s0 * 8 + l8];
                a0[0] = h2add(a0[0], as_h2(r0.x));
                a0[1] = h2add(a0[1], as_h2(r0.y));
                a0[2] = h2add(a0[2], as_h2(r0.z));
                a0[3] = h2add(a0[3], as_h2(r0.w));
            }
            if (j1 < cnt) {
                uint4 r1 = xh4[s1 * 8 + l8];
                a1[0] = h2add(a1[0], as_h2(r1.x));
                a1[1] = h2add(a1[1], as_h2(r1.y));
                a1[2] = h2add(a1[2], as_h2(r1.z));
                a1[3] = h2add(a1[3], as_h2(r1.w));
            }
        }
    }
    #pragma unroll
    for (int k = 0; k < 4; k++) a0[k] = h2add(a0[k], a1[k]);

    // cross-group reduce
    #pragma unroll
    for (int off = 8; off <= 16; off <<= 1) {
        #pragma unroll
        for (int k = 0; k < 4; k++) {
            unsigned int o = __shfl_xor_sync(0xffffffff, as_u(a0[k]), off);
            a0[k] = h2add(a0[k], as_h2(o));
        }
    }

    if (g == 0) {   // lanes 0..7 hold the full row sum
        float din = g_dinv[d];
        uint4 u;
        #pragma unroll
        for (int k = 0; k < 4; k++) {
            float2 f = __half22float2(a0[k]);
            __half2 h = __floats2half2_rn(f.x * din, f.y * din);
            ((unsigned int*)&u)[k] = as_u(h);
        }
        ((uint4*)g_ah)[d * 8 + l8] = u;
    }
}

// ---------------------------------------------------------------------------
// z[n] = dinv[n] * dot(relu(ah[n] @ W1 + b1), w2l) via mma.m16n8k16.
#define W1T_STRIDE 72
__global__ void __launch_bounds__(256) k_gemm(const float* __restrict__ b1, int n) {
    __shared__ __half w1s[128 * W1T_STRIDE];   // 18 KB
    __shared__ float  b1s[128];
    __shared__ float  ws[128];

    int tid = threadIdx.x;
    for (int i = tid; i < 2048; i += 256) {
        int nl = i >> 4, kq = i & 15;
        *(uint2*)&w1s[nl * W1T_STRIDE + kq * 4] = ((const uint2*)g_w1t)[i];
    }
    if (tid < 128) { b1s[tid] = b1[tid]; ws[tid] = g_w2l[tid]; }
    __syncthreads();

    int w = tid >> 5, lane = tid & 31;
    int gid = lane >> 2, tg = lane & 3;
    int n0 = (blockIdx.x * 8 + w) * 16;
    if (n0 >= n) return;

    int rA = min(n0 + gid, n - 1);
    int rB = min(n0 + gid + 8, n - 1);

    unsigned int a[4][4];
    #pragma unroll
    for (int kk = 0; kk < 4; kk++) {
        int baseA = rA * 32 + kk * 8;
        int baseB = rB * 32 + kk * 8;
        a[kk][0] = g_ah[baseA + tg];
        a[kk][1] = g_ah[baseB + tg];
        a[kk][2] = g_ah[baseA + tg + 4];
        a[kk][3] = g_ah[baseB + tg + 4];
    }

    float zp0 = 0.f, zp1 = 0.f;
    #pragma unroll
    for (int nc = 0; nc < 16; nc++) {
        float c0 = 0.f, c1 = 0.f, c2 = 0.f, c3 = 0.f;
        int nrow = nc * 8 + gid;
        const unsigned int* w1row = (const unsigned int*)&w1s[nrow * W1T_STRIDE];
        #pragma unroll
        for (int kk = 0; kk < 4; kk++) {
            unsigned int b0 = w1row[kk * 8 + tg];
            unsigned int b1r = w1row[kk * 8 + tg + 4];
            asm volatile(
                "mma.sync.aligned.m16n8k16.row.col.f32.f16.f16.f32 "
                "{%0,%1,%2,%3}, {%4,%5,%6,%7}, {%8,%9}, {%0,%1,%2,%3};"
                : "+f"(c0), "+f"(c1), "+f"(c2), "+f"(c3)
                : "r"(a[kk][0]), "r"(a[kk][1]), "r"(a[kk][2]), "r"(a[kk][3]),
                  "r"(b0), "r"(b1r));
        }
        int j0 = nc * 8 + tg * 2;
        float2 bb = *(const float2*)&b1s[j0];
        float2 ww = *(const float2*)&ws[j0];
        zp0 += fmaxf(c0 + bb.x, 0.f) * ww.x + fmaxf(c1 + bb.y, 0.f) * ww.y;
        zp1 += fmaxf(c2 + bb.x, 0.f) * ww.x + fmaxf(c3 + bb.y, 0.f) * ww.y;
    }

    #pragma unroll
    for (int o = 1; o < 4; o <<= 1) {
        zp0 += __shfl_xor_sync(0xffffffff, zp0, o);
        zp1 += __shfl_xor_sync(0xffffffff, zp1, o);
    }
    if (tg == 0) {
        int nodeA = n0 + gid, nodeB = n0 + gid + 8;
        if (nodeA < n) g_z[nodeA] = g_dinv[nodeA] * zp0;
        if (nodeB < n) g_z[nodeB] = g_dinv[nodeB] * zp1;
    }
}

// ---------------------------------------------------------------------------
// out[d] = dinv[d]*(sum z[src] + z[d]) + cb. int4 loads of 4 indices/step.
// Also re-zeroes g_count so the next kernel_launch starts clean.
__global__ void k_agg2(float* __restrict__ out, int n) {
    int d = blockIdx.x * blockDim.x + threadIdx.x;
    if (d >= n) return;
    float s = g_z[d];
    const int4* bkt = (const int4*)&g_csrc[d * CAP];
    int deg = min(g_count[d], CAP);
    int nq = (deg + 3) >> 2;
    for (int q = 0; q < nq; q++) {
        int4 o = bkt[q];
        int i0 = q * 4;
        int s0 = min(max(o.x, 0), n - 1);
        int s1 = min(max(o.y, 0), n - 1);
        int s2 = min(max(o.z, 0), n - 1);
        int s3 = min(max(o.w, 0), n - 1);
        float v = 0.f;
        if (i0 + 0 < deg) v += g_z[s0];
        if (i0 + 1 < deg) v += g_z[s1];
        if (i0 + 2 < deg) v += g_z[s2];
        if (i0 + 3 < deg) v += g_z[s3];
        s += v;
    }
    out[d] = g_dinv[d] * s + g_cb;
    g_count[d] = 0;   // self-cleaning: counts zero for next launch
}

// ---------------------------------------------------------------------------
extern "C" void kernel_launch(void* const* d_in, const int* in_sizes, int n_in,
                              void* d_out, int out_size) {
    const float* x   = (const float*)d_in[0];
    const void*  ei  = d_in[1];
    const float* W1  = (const float*)d_in[2];
    const float* b1  = (const float*)d_in[3];
    const float* W2  = (const float*)d_in[4];
    const float* b2  = (const float*)d_in[5];
    const float* Wl  = (const float*)d_in[6];
    const float* bl  = (const float*)d_in[7];
    float*       out = (float*)d_out;

    int n = in_sizes[0] / 64;
    int E = in_sizes[1] / 2;

    int nb = (n + 255) / 256;
    int eb = (E + 255) / 256;
    int cb = (n * 16 + 255) / 256;

    k_prep0<<<2, 256>>>((const int*)ei, W1, W2, b2, Wl, bl);
    k_fill <<<eb, 256>>>(ei, E, n);
    k_conv <<<cb, 256>>>(x, n);
    k_agg1 <<<(n + 7) / 8, 256>>>(n);
    k_gemm <<<(n + 127) / 128, 256>>>(b1, n);
    k_agg2 <<<nb, 256>>>(out, n);
}

// round 16
// speedup vs baseline: 1.1216x; 1.0027x over previous
#include <cuda_runtime.h>
#include <cuda_fp16.h>

// GCN_3831110828646 — restructured GCN, bucketed edges + prescaled fp16 + HMMA gemm:
//   xh[s] = fp16( x[s] * dinv[s] )
//   ah[d] = fp16( dinv[d] * ( sum_b xh[s_b] + xh[d] ) )      (8-lane rows; uniform SHFL.IDX loop)
//   z[n]  = dinv[n] * dot( relu(ah[n] @ W1h + b1), W2@Wl )   (mma.m16n8k16 + fused epilogue)
//   out[d]= dinv[d] * ( sum_b z[s_b] + z[d] ) + (b2@Wl + bl) (scalar gather, int4 idx loads)
// Self-cleaning counts: g_count starts zero (BSS) and k_agg2 re-zeroes after use.

#define NMAX 100000
#define EMAX 1600000
#define CAP  64

__device__ int          g_idx64;
__device__ int          g_count[NMAX];       // ALWAYS zero at kernel_launch entry
__device__ float        g_dinv[NMAX];
__device__ int          g_csrc[NMAX * CAP];  // 25.6 MB bucket array
__device__ unsigned int g_xh[NMAX * 32];     // prescaled x fp16: 32 half2 per row (128B)
__device__ unsigned int g_ah[NMAX * 32];     // aggregated a fp16: 32 half2 per row
__device__ __half       g_w1t[128 * 64];     // W1 transposed [n][k] fp16
__device__ float        g_z[NMAX];
__device__ float        g_w2l[128];
__device__ float        g_cb;

__device__ __forceinline__ __half2 h2add(__half2 a, __half2 b) { return __hadd2(a, b); }
__device__ __forceinline__ __half2 as_h2(unsigned int u) { return *(__half2*)&u; }
__device__ __forceinline__ unsigned int as_u(__half2 h) { return *(unsigned int*)&h; }

// ---------------------------------------------------------------------------
// 2 blocks only: block 0 = w2l/cb + dtype detect; block 1 = W1 fp16 transpose.
__global__ void k_prep0(const int* __restrict__ ei,
                        const float* __restrict__ W1,
                        const float* __restrict__ W2, const float* __restrict__ b2,
                        const float* __restrict__ Wl, const float* __restrict__ bl) {
    if (blockIdx.x == 0) {
        int c = threadIdx.x;
        if (c < 128) {
            float s = 0.f;
            for (int k = 0; k < 100; k++) s += W2[c * 100 + k] * Wl[k];
            g_w2l[c] = s;
        }
        if (c == 0) {
            float t = 0.f;
            for (int k = 0; k < 100; k++) t += b2[k] * Wl[k];
            g_cb = t + bl[0];
            int is64 = 1;
            for (int j = 0; j < 64; j++)
                if (ei[2 * j + 1] != 0) { is64 = 0; break; }
            g_idx64 = is64;
        }
    } else {
        for (int i = threadIdx.x; i < 128 * 64; i += blockDim.x) {
            int nl = i >> 6, k = i & 63;
            g_w1t[i] = __float2half(W1[k * 128 + nl]);   // W1t[n][k] = W1[k][n]
        }
    }
}

__device__ __forceinline__ int load_src(const void* ei, int E, int e, int n) {
    int v = g_idx64 ? (int)((const long long*)ei)[e] : ((const int*)ei)[e];
    return min(max(v, 0), n - 1);
}
__device__ __forceinline__ int load_dst(const void* ei, int E, int e, int n) {
    int v = g_idx64 ? (int)((const long long*)ei)[E + e] : ((const int*)ei)[E + e];
    return min(max(v, 0), n - 1);
}

// 4 edges per thread: batched index loads up front, then 4 INDEPENDENT
// atomic->store chains in flight (fills the ATOMG latency that made the
// 1-edge version issue-bound at 7%).
__global__ void k_fill(const void* __restrict__ ei, int E, int n) {
    int base = (blockIdx.x * blockDim.x + threadIdx.x) * 4;
    if (base >= E) return;
    int m = min(4, E - base);
    int d[4], s[4];
    #pragma unroll
    for (int k = 0; k < 4; k++) {
        int e = base + ((k < m) ? k : 0);      // clamp within-range for safe load
        d[k] = load_dst(ei, E, e, n);
        s[k] = load_src(ei, E, e, n);
    }
    #pragma unroll
    for (int k = 0; k < 4; k++) {
        if (k < m) {
            int p = atomicAdd(&g_count[d[k]], 1);
            if (p < CAP) g_csrc[d[k] * CAP + p] = s[k];
        }
    }
}

// x -> fp16 prescaled by dinv[row]; store dinv. One float4 per thread.
__global__ void k_conv(const float* __restrict__ x, int n) {
    int i = blockIdx.x * blockDim.x + threadIdx.x;   // over n*16 float4s
    if (i >= n * 16) return;
    int row = i >> 4;
    float din = rsqrtf((float)(min(g_count[row], CAP) + 1));
    float4 v = ((const float4*)x)[i];
    __half2 h0 = __floats2half2_rn(v.x * din, v.y * din);
    __half2 h1 = __floats2half2_rn(v.z * din, v.w * din);
    uint2 u;
    u.x = *(unsigned int*)&h0;
    u.y = *(unsigned int*)&h1;
    ((uint2*)g_xh)[i] = u;
    if ((i & 15) == 0) g_dinv[row] = din;
}

// ---------------------------------------------------------------------------
// Aggregation (proven form, 32 regs / 83% occ): one warp per node,
// row = 8 lanes x uint4 (128B); 4 groups take different edges per instruction.
// 32 bucket indices preloaded in ONE LDG; SHFL.IDX with warp-uniform trip
// count; only loads/adds predicated.
__global__ void k_agg1(int n) {
    int warp = (blockIdx.x * blockDim.x + threadIdx.x) >> 5;
    int lane = threadIdx.x & 31;
    if (warp >= n) return;
    int d = warp;
    int g = lane >> 3, l8 = lane & 7;

    const uint4* xh4 = (const uint4*)g_xh;

    uint4 sv = make_uint4(0u, 0u, 0u, 0u);
    if (g == 0) sv = xh4[d * 8 + l8];            // self term (prescaled by dinv[d])
    __half2 a0[4] = { as_h2(sv.x), as_h2(sv.y), as_h2(sv.z), as_h2(sv.w) };
    __half2 a1[4];
    #pragma unroll
    for (int k = 0; k < 4; k++) a1[k] = as_h2(0u);

    int bko = d * CAP;
    int deg = min(g_count[d], CAP);
    for (int base = 0; base < deg; base += 32) {
        int cnt = min(32, deg - base);             // warp-uniform
        int idx = 0;
        if (lane < cnt) idx = g_csrc[bko + base + lane];   // one LDG: 32 indices
        int nsteps = (cnt + 7) >> 3;               // warp-uniform trip count
        for (int t = 0; t < nsteps; t++) {
            int j0 = g + t * 8;
            int j1 = j0 + 4;
            int s0 = __shfl_sync(0xffffffff, idx, j0);   // uniform: all lanes
            int s1 = __shfl_sync(0xffffffff, idx, j1);
            s0 = min(max(s0, 0), n - 1);
            s1 = min(max(s1, 0), n - 1);
            if (j0 < cnt) {
                uint4 r0 = xh4[s0 * 8 + l8];
                a0[0] = h2add(a0[0], as_h2(r0.x));
                a0[1] = h2add(a0[1], as_h2(r0.y));
                a0[2] = h2add(a0[2], as_h2(r0.z));
                a0[3] = h2add(a0[3], as_h2(r0.w));
            }
            if (j1 < cnt) {
                uint4 r1 = xh4[s1 * 8 + l8];
                a1[0] = h2add(a1[0], as_h2(r1.x));
                a1[1] = h2add(a1[1], as_h2(r1.y));
                a1[2] = h2add(a1[2], as_h2(r1.z));
                a1[3] = h2add(a1[3], as_h2(r1.w));
            }
        }
    }
    #pragma unroll
    for (int k = 0; k < 4; k++) a0[k] = h2add(a0[k], a1[k]);

    // cross-group reduce
    #pragma unroll
    for (int off = 8; off <= 16; off <<= 1) {
        #pragma unroll
        for (int k = 0; k < 4; k++) {
            unsigned int o = __shfl_xor_sync(0xffffffff, as_u(a0[k]), off);
            a0[k] = h2add(a0[k], as_h2(o));
        }
    }

    if (g == 0) {   // lanes 0..7 hold the full row sum
        float din = g_dinv[d];
        uint4 u;
        #pragma unroll
        for (int k = 0; k < 4; k++) {
            float2 f = __half22float2(a0[k]);
            __half2 h = __floats2half2_rn(f.x * din, f.y * din);
            ((unsigned int*)&u)[k] = as_u(h);
        }
        ((uint4*)g_ah)[d * 8 + l8] = u;
    }
}

// ---------------------------------------------------------------------------
// z[n] = dinv[n] * dot(relu(ah[n] @ W1 + b1), w2l) via mma.m16n8k16.
#define W1T_STRIDE 72
__global__ void __launch_bounds__(256) k_gemm(const float* __restrict__ b1, int n) {
    __shared__ __half w1s[128 * W1T_STRIDE];   // 18 KB
    __shared__ float  b1s[128];
    __shared__ float  ws[128];

    int tid = threadIdx.x;
    for (int i = tid; i < 2048; i += 256) {
        int nl = i >> 4, kq = i & 15;
        *(uint2*)&w1s[nl * W1T_STRIDE + kq * 4] = ((const uint2*)g_w1t)[i];
    }
    if (tid < 128) { b1s[tid] = b1[tid]; ws[tid] = g_w2l[tid]; }
    __syncthreads();

    int w = tid >> 5, lane = tid & 31;
    int gid = lane >> 2, tg = lane & 3;
    int n0 = (blockIdx.x * 8 + w) * 16;
    if (n0 >= n) return;

    int rA = min(n0 + gid, n - 1);
    int rB = min(n0 + gid + 8, n - 1);

    unsigned int a[4][4];
    #pragma unroll
    for (int kk = 0; kk < 4; kk++) {
        int baseA = rA * 32 + kk * 8;
        int baseB = rB * 32 + kk * 8;
        a[kk][0] = g_ah[baseA + tg];
        a[kk][1] = g_ah[baseB + tg];
        a[kk][2] = g_ah[baseA + tg + 4];
        a[kk][3] = g_ah[baseB + tg + 4];
    }

    float zp0 = 0.f, zp1 = 0.f;
    #pragma unroll
    for (int nc = 0; nc < 16; nc++) {
        float c0 = 0.f, c1 = 0.f, c2 = 0.f, c3 = 0.f;
        int nrow = nc * 8 + gid;
        const unsigned int* w1row = (const unsigned int*)&w1s[nrow * W1T_STRIDE];
        #pragma unroll
        for (int kk = 0; kk < 4; kk++) {
            unsigned int b0 = w1row[kk * 8 + tg];
            unsigned int b1r = w1row[kk * 8 + tg + 4];
            asm volatile(
                "mma.sync.aligned.m16n8k16.row.col.f32.f16.f16.f32 "
                "{%0,%1,%2,%3}, {%4,%5,%6,%7}, {%8,%9}, {%0,%1,%2,%3};"
                : "+f"(c0), "+f"(c1), "+f"(c2), "+f"(c3)
                : "r"(a[kk][0]), "r"(a[kk][1]), "r"(a[kk][2]), "r"(a[kk][3]),
                  "r"(b0), "r"(b1r));
        }
        int j0 = nc * 8 + tg * 2;
        float2 bb = *(const float2*)&b1s[j0];
        float2 ww = *(const float2*)&ws[j0];
        zp0 += fmaxf(c0 + bb.x, 0.f) * ww.x + fmaxf(c1 + bb.y, 0.f) * ww.y;
        zp1 += fmaxf(c2 + bb.x, 0.f) * ww.x + fmaxf(c3 + bb.y, 0.f) * ww.y;
    }

    #pragma unroll
    for (int o = 1; o < 4; o <<= 1) {
        zp0 += __shfl_xor_sync(0xffffffff, zp0, o);
        zp1 += __shfl_xor_sync(0xffffffff, zp1, o);
    }
    if (tg == 0) {
        int nodeA = n0 + gid, nodeB = n0 + gid + 8;
        if (nodeA < n) g_z[nodeA] = g_dinv[nodeA] * zp0;
        if (nodeB < n) g_z[nodeB] = g_dinv[nodeB] * zp1;
    }
}

// ---------------------------------------------------------------------------
// out[d] = dinv[d]*(sum z[src] + z[d]) + cb. int4 loads of 4 indices/step.
// Also re-zeroes g_count so the next kernel_launch starts clean.
__global__ void k_agg2(float* __restrict__ out, int n) {
    int d = blockIdx.x * blockDim.x + threadIdx.x;
    if (d >= n) return;
    float s = g_z[d];
    const int4* bkt = (const int4*)&g_csrc[d * CAP];
    int deg = min(g_count[d], CAP);
    int nq = (deg + 3) >> 2;
    for (int q = 0; q < nq; q++) {
        int4 o = bkt[q];
        int i0 = q * 4;
        int s0 = min(max(o.x, 0), n - 1);
        int s1 = min(max(o.y, 0), n - 1);
        int s2 = min(max(o.z, 0), n - 1);
        int s3 = min(max(o.w, 0), n - 1);
        float v = 0.f;
        if (i0 + 0 < deg) v += g_z[s0];
        if (i0 + 1 < deg) v += g_z[s1];
        if (i0 + 2 < deg) v += g_z[s2];
        if (i0 + 3 < deg) v += g_z[s3];
        s += v;
    }
    out[d] = g_dinv[d] * s + g_cb;
    g_count[d] = 0;   // self-cleaning: counts zero for next launch
}

// ---------------------------------------------------------------------------
extern "C" void kernel_launch(void* const* d_in, const int* in_sizes, int n_in,
                              void* d_out, int out_size) {
    const float* x   = (const float*)d_in[0];
    const void*  ei  = d_in[1];
    const float* W1  = (const float*)d_in[2];
    const float* b1  = (const float*)d_in[3];
    const float* W2  = (const float*)d_in[4];
    const float* b2  = (const float*)d_in[5];
    const float* Wl  = (const float*)d_in[6];
    const float* bl  = (const float*)d_in[7];
    float*       out = (float*)d_out;

    int n = in_sizes[0] / 64;
    int E = in_sizes[1] / 2;

    int nb = (n + 255) / 256;
    int eb = (E / 4 + 255) / 256;
    int cb = (n * 16 + 255) / 256;

    k_prep0<<<2, 256>>>((const int*)ei, W1, W2, b2, Wl, bl);
    k_fill <<<eb, 256>>>(ei, E, n);
    k_conv <<<cb, 256>>>(x, n);
    k_agg1 <<<(n + 7) / 8, 256>>>(n);
    k_gemm <<<(n + 127) / 128, 256>>>(b1, n);
    k_agg2 <<<nb, 256>>>(out, n);
}

// round 17
// speedup vs baseline: 1.2420x; 1.1074x over previous
#include <cuda_runtime.h>
#include <cuda_fp16.h>

// GCN_3831110828646 — restructured GCN, bucketed edges + prescaled fp16 + HMMA gemm:
//   xh[s] = fp16( x[s] * dinv[s] )
//   ah[d] = fp16( dinv[d] * ( sum_b xh[s_b] + xh[d] ) )      (4 nodes/warp, group-per-node)
//   z[n]  = dinv[n] * dot( relu(ah[n] @ W1h + b1), W2@Wl )   (mma.m16n8k16 + fused epilogue)
//   out[d]= dinv[d] * ( sum_b z[s_b] + z[d] ) + (b2@Wl + bl) (scalar gather, int4 idx loads)
// Self-cleaning counts: g_count starts zero (BSS) and k_agg2 re-zeroes after use.
// Weight prep (w2l/cb, W1 fp16 transpose) rides as blocks 0,1 of k_fill.

#define NMAX 100000
#define EMAX 1600000
#define CAP  64

__device__ int          g_count[NMAX];       // ALWAYS zero at kernel_launch entry
__device__ float        g_dinv[NMAX];
__device__ int          g_csrc[NMAX * CAP];  // 25.6 MB bucket array
__device__ unsigned int g_xh[NMAX * 32];     // prescaled x fp16: 32 half2 per row (128B)
__device__ unsigned int g_ah[NMAX * 32];     // aggregated a fp16: 32 half2 per row
__device__ __half       g_w1t[128 * 64];     // W1 transposed [n][k] fp16
__device__ float        g_z[NMAX];
__device__ float        g_w2l[128];
__device__ float        g_cb;

__device__ __forceinline__ __half2 h2add(__half2 a, __half2 b) { return __hadd2(a, b); }
__device__ __forceinline__ __half2 as_h2(unsigned int u) { return *(__half2*)&u; }
__device__ __forceinline__ unsigned int as_u(__half2 h) { return *(unsigned int*)&h; }

__device__ __forceinline__ int ld_idx(const void* ei, int is64, int e, int n) {
    int v = is64 ? (int)((const long long*)ei)[e] : ((const int*)ei)[e];
    return min(max(v, 0), n - 1);
}

// ---------------------------------------------------------------------------
// Fill + weight prep. Block 0: w2l/cb. Block 1: W1 -> fp16 transpose.
// Blocks 2+: 4 edges/thread bucket scatter. Every block self-detects dtype.
__global__ void k_fill(const void* __restrict__ ei, int E, int n,
                       const float* __restrict__ W1,
                       const float* __restrict__ W2, const float* __restrict__ b2,
                       const float* __restrict__ Wl, const float* __restrict__ bl) {
    int tid = threadIdx.x;
    // dtype detect: int64 indices < 2^31 have all-zero odd 32-bit words
    int wrd = (tid < 64) ? ((const int*)ei)[2 * tid + 1] : 0;
    int is64 = !__syncthreads_or(wrd != 0);

    if (blockIdx.x == 0) {
        if (tid < 128) {
            float s = 0.f;
            for (int k = 0; k < 100; k++) s += W2[tid * 100 + k] * Wl[k];
            g_w2l[tid] = s;
        }
        if (tid == 0) {
            float t = 0.f;
            for (int k = 0; k < 100; k++) t += b2[k] * Wl[k];
            g_cb = t + bl[0];
        }
        return;
    }
    if (blockIdx.x == 1) {
        for (int i = tid; i < 128 * 64; i += blockDim.x) {
            int nl = i >> 6, k = i & 63;
            g_w1t[i] = __float2half(W1[k * 128 + nl]);   // W1t[n][k] = W1[k][n]
        }
        return;
    }

    int base = ((blockIdx.x - 2) * blockDim.x + tid) * 4;
    if (base >= E) return;
    int m = min(4, E - base);
    int d[4], s[4];
    #pragma unroll
    for (int k = 0; k < 4; k++) {
        int e = base + ((k < m) ? k : 0);
        d[k] = ld_idx(ei, is64, E + e, n);   // dst half
        s[k] = ld_idx(ei, is64, e, n);       // src half
    }
    #pragma unroll
    for (int k = 0; k < 4; k++) {
        if (k < m) {
            int p = atomicAdd(&g_count[d[k]], 1);
            if (p < CAP) g_csrc[d[k] * CAP + p] = s[k];
        }
    }
}

// x -> fp16 prescaled by dinv[row]; store dinv. One float4 per thread.
__global__ void k_conv(const float* __restrict__ x, int n) {
    int i = blockIdx.x * blockDim.x + threadIdx.x;   // over n*16 float4s
    if (i >= n * 16) return;
    int row = i >> 4;
    float din = rsqrtf((float)(min(g_count[row], CAP) + 1));
    float4 v = ((const float4*)x)[i];
    __half2 h0 = __floats2half2_rn(v.x * din, v.y * din);
    __half2 h1 = __floats2half2_rn(v.z * din, v.w * din);
    uint2 u;
    u.x = *(unsigned int*)&h0;
    u.y = *(unsigned int*)&h1;
    ((uint2*)g_xh)[i] = u;
    if ((i & 15) == 0) g_dinv[row] = din;
}

// ---------------------------------------------------------------------------
// Aggregation: 4 nodes per warp; each 8-lane group owns one node end-to-end
// (no cross-group reduce). Row = 8 lanes x uint4 (128B). Loop bound is the
// warp-uniform max degree of the 4 nodes; all SHFLs execute unconditionally
// (full warp), only loads/adds are predicated. fp16 pair-accumulators are
// flushed to fp32 every 8 edges (chain depth <= 5).
__global__ void k_agg1(int n) {
    int wg = (blockIdx.x * blockDim.x + threadIdx.x) >> 5;
    int lane = threadIdx.x & 31;
    if (wg * 4 >= n) return;                       // warp-uniform exit
    int g = lane >> 3, l8 = lane & 7;
    int node = wg * 4 + g;
    bool valid = node < n;
    int nodeC = min(node, n - 1);

    const uint4* xh4 = (const uint4*)g_xh;

    int deg = valid ? min(g_count[nodeC], CAP) : 0;
    int mdeg = deg;
    mdeg = max(mdeg, __shfl_xor_sync(0xffffffff, mdeg, 8));
    mdeg = max(mdeg, __shfl_xor_sync(0xffffffff, mdeg, 16));   // max over 4 groups

    // fp32 accumulator initialized with the self term (prescaled by dinv)
    float facc[8];
    {
        uint4 sv = xh4[nodeC * 8 + l8];
        float2 f0 = __half22float2(as_h2(sv.x));
        float2 f1 = __half22float2(as_h2(sv.y));
        float2 f2 = __half22float2(as_h2(sv.z));
        float2 f3 = __half22float2(as_h2(sv.w));
        facc[0] = f0.x; facc[1] = f0.y; facc[2] = f1.x; facc[3] = f1.y;
        facc[4] = f2.x; facc[5] = f2.y; facc[6] = f3.x; facc[7] = f3.y;
    }

    int bko = nodeC * CAP;
    int glane = lane & 24;                          // group base lane (g*8)
    int nrounds = (mdeg + 7) >> 3;                  // warp-uniform
    for (int r = 0; r < nrounds; r++) {
        int idx = g_csrc[bko + r * 8 + l8];         // 32 indices, group-blocked
        __half2 a0[4], a1[4];
        #pragma unroll
        for (int k = 0; k < 4; k++) { a0[k] = as_h2(0u); a1[k] = as_h2(0u); }
        #pragma unroll
        for (int t = 0; t < 4; t++) {
            int j0 = 2 * t, j1 = 2 * t + 1;
            int s0 = __shfl_sync(0xffffffff, idx, glane + j0);  // all lanes execute
            int s1 = __shfl_sync(0xffffffff, idx, glane + j1);
            s0 = min(max(s0, 0), n - 1);
            s1 = min(max(s1, 0), n - 1);
            int e0 = r * 8 + j0, e1 = r * 8 + j1;
            if (e0 < deg) {
                uint4 r0 = xh4[s0 * 8 + l8];
                a0[0] = h2add(a0[0], as_h2(r0.x));
                a0[1] = h2add(a0[1], as_h2(r0.y));
                a0[2] = h2add(a0[2], as_h2(r0.z));
                a0[3] = h2add(a0[3], as_h2(r0.w));
            }
            if (e1 < deg) {
                uint4 r1 = xh4[s1 * 8 + l8];
                a1[0] = h2add(a1[0], as_h2(r1.x));
                a1[1] = h2add(a1[1], as_h2(r1.y));
                a1[2] = h2add(a1[2], as_h2(r1.z));
                a1[3] = h2add(a1[3], as_h2(r1.w));
            }
        }
        // flush to fp32
        #pragma unroll
        for (int k = 0; k < 4; k++) {
            float2 f = __half22float2(h2add(a0[k], a1[k]));
            facc[2 * k]     += f.x;
            facc[2 * k + 1] += f.y;
        }
    }

    if (valid) {
        float din = g_dinv[nodeC];
        uint4 u;
        #pragma unroll
        for (int k = 0; k < 4; k++) {
            __half2 h = __floats2half2_rn(facc[2 * k] * din, facc[2 * k + 1] * din);
            ((unsigned int*)&u)[k] = as_u(h);
        }
        ((uint4*)g_ah)[node * 8 + l8] = u;          // 1 STG.128 for 4 nodes
    }
}

// ---------------------------------------------------------------------------
// z[n] = dinv[n] * dot(relu(ah[n] @ W1 + b1), w2l) via mma.m16n8k16.
#define W1T_STRIDE 72
__global__ void __launch_bounds__(256) k_gemm(const float* __restrict__ b1, int n) {
    __shared__ __half w1s[128 * W1T_STRIDE];   // 18 KB
    __shared__ float  b1s[128];
    __shared__ float  ws[128];

    int tid = threadIdx.x;
    for (int i = tid; i < 2048; i += 256) {
        int nl = i >> 4, kq = i & 15;
        *(uint2*)&w1s[nl * W1T_STRIDE + kq * 4] = ((const uint2*)g_w1t)[i];
    }
    if (tid < 128) { b1s[tid] = b1[tid]; ws[tid] = g_w2l[tid]; }
    __syncthreads();

    int w = tid >> 5, lane = tid & 31;
    int gid = lane >> 2, tg = lane & 3;
    int n0 = (blockIdx.x * 8 + w) * 16;
    if (n0 >= n) return;

    int rA = min(n0 + gid, n - 1);
    int rB = min(n0 + gid + 8, n - 1);

    unsigned int a[4][4];
    #pragma unroll
    for (int kk = 0; kk < 4; kk++) {
        int baseA = rA * 32 + kk * 8;
        int baseB = rB * 32 + kk * 8;
        a[kk][0] = g_ah[baseA + tg];
        a[kk][1] = g_ah[baseB + tg];
        a[kk][2] = g_ah[baseA + tg + 4];
        a[kk][3] = g_ah[baseB + tg + 4];
    }

    float zp0 = 0.f, zp1 = 0.f;
    #pragma unroll
    for (int nc = 0; nc < 16; nc++) {
        float c0 = 0.f, c1 = 0.f, c2 = 0.f, c3 = 0.f;
        int nrow = nc * 8 + gid;
        const unsigned int* w1row = (const unsigned int*)&w1s[nrow * W1T_STRIDE];
        #pragma unroll
        for (int kk = 0; kk < 4; kk++) {
            unsigned int b0 = w1row[kk * 8 + tg];
            unsigned int b1r = w1row[kk * 8 + tg + 4];
            asm volatile(
                "mma.sync.aligned.m16n8k16.row.col.f32.f16.f16.f32 "
                "{%0,%1,%2,%3}, {%4,%5,%6,%7}, {%8,%9}, {%0,%1,%2,%3};"
                : "+f"(c0), "+f"(c1), "+f"(c2), "+f"(c3)
                : "r"(a[kk][0]), "r"(a[kk][1]), "r"(a[kk][2]), "r"(a[kk][3]),
                  "r"(b0), "r"(b1r));
        }
        int j0 = nc * 8 + tg * 2;
        float2 bb = *(const float2*)&b1s[j0];
        float2 ww = *(const float2*)&ws[j0];
        zp0 += fmaxf(c0 + bb.x, 0.f) * ww.x + fmaxf(c1 + bb.y, 0.f) * ww.y;
        zp1 += fmaxf(c2 + bb.x, 0.f) * ww.x + fmaxf(c3 + bb.y, 0.f) * ww.y;
    }

    #pragma unroll
    for (int o = 1; o < 4; o <<= 1) {
        zp0 += __shfl_xor_sync(0xffffffff, zp0, o);
        zp1 += __shfl_xor_sync(0xffffffff, zp1, o);
    }
    if (tg == 0) {
        int nodeA = n0 + gid, nodeB = n0 + gid + 8;
        if (nodeA < n) g_z[nodeA] = g_dinv[nodeA] * zp0;
        if (nodeB < n) g_z[nodeB] = g_dinv[nodeB] * zp1;
    }
}

// ---------------------------------------------------------------------------
// out[d] = dinv[d]*(sum z[src] + z[d]) + cb. int4 loads of 4 indices/step.
// Also re-zeroes g_count so the next kernel_launch starts clean.
__global__ void k_agg2(float* __restrict__ out, int n) {
    int d = blockIdx.x * blockDim.x + threadIdx.x;
    if (d >= n) return;
    float s = g_z[d];
    const int4* bkt = (const int4*)&g_csrc[d * CAP];
    int deg = min(g_count[d], CAP);
    int nq = (deg + 3) >> 2;
    for (int q = 0; q < nq; q++) {
        int4 o = bkt[q];
        int i0 = q * 4;
        int s0 = min(max(o.x, 0), n - 1);
        int s1 = min(max(o.y, 0), n - 1);
        int s2 = min(max(o.z, 0), n - 1);
        int s3 = min(max(o.w, 0), n - 1);
        float v = 0.f;
        if (i0 + 0 < deg) v += g_z[s0];
        if (i0 + 1 < deg) v += g_z[s1];
        if (i0 + 2 < deg) v += g_z[s2];
        if (i0 + 3 < deg) v += g_z[s3];
        s += v;
    }
    out[d] = g_dinv[d] * s + g_cb;
    g_count[d] = 0;   // self-cleaning: counts zero for next launch
}

// ---------------------------------------------------------------------------
extern "C" void kernel_launch(void* const* d_in, const int* in_sizes, int n_in,
                              void* d_out, int out_size) {
    const float* x   = (const float*)d_in[0];
    const void*  ei  = d_in[1];
    const float* W1  = (const float*)d_in[2];
    const float* b1  = (const float*)d_in[3];
    const float* W2  = (const float*)d_in[4];
    const float* b2  = (const float*)d_in[5];
    const float* Wl  = (const float*)d_in[6];
    const float* bl  = (const float*)d_in[7];
    float*       out = (float*)d_out;

    int n = in_sizes[0] / 64;
    int E = in_sizes[1] / 2;

    int nb = (n + 255) / 256;
    int eb = (E / 4 + 255) / 256 + 2;          // +2 prep blocks
    int cb = (n * 16 + 255) / 256;
    int ab = (n + 31) / 32;                    // 4 nodes/warp, 8 warps/block

    k_fill <<<eb, 256>>>(ei, E, n, W1, W2, b2, Wl, bl);
    k_conv <<<cb, 256>>>(x, n);
    k_agg1 <<<ab, 256>>>(n);
    k_gemm <<<(n + 127) / 128, 256>>>(b1, n);
    k_agg2 <<<nb, 256>>>(out, n);
}